// round 8
// baseline (speedup 1.0000x reference)
#include <cuda_runtime.h>
#include <stdint.h>
#include <float.h>

#define NROWS 8192
#define NCOLS 1000
#define NT 256
#define WPB 8                 // warps (rows) per block
#define NB (NROWS / WPB)      // 1024 blocks
#define NQ 26
#define NSTAGE 3              // cp.async ring depth per warp

typedef unsigned long long u64;
typedef unsigned int u32;

__device__ float g_ce[NROWS];
__device__ float g_a[NROWS];
__device__ float g_mx[NROWS];
__device__ int   g_ticket;    // zero-init; reset by last block each run

__device__ __forceinline__ u64 pk(float lo, float hi) {
    u64 r; asm("mov.b64 %0, {%1, %2};" : "=l"(r) : "f"(lo), "f"(hi)); return r;
}
__device__ __forceinline__ float2 upk(u64 v) {
    float2 f; asm("mov.b64 {%0, %1}, %2;" : "=f"(f.x), "=f"(f.y) : "l"(v)); return f;
}
__device__ __forceinline__ u64 vadd(u64 a, u64 b) {
    u64 r; asm("add.rn.f32x2 %0, %1, %2;" : "=l"(r) : "l"(a), "l"(b)); return r;
}
__device__ __forceinline__ u64 vmul(u64 a, u64 b) {
    u64 r; asm("mul.rn.f32x2 %0, %1, %2;" : "=l"(r) : "l"(a), "l"(b)); return r;
}
__device__ __forceinline__ u64 vfma(u64 a, u64 b, u64 c) {
    u64 r; asm("fma.rn.f32x2 %0, %1, %2, %3;" : "=l"(r) : "l"(a), "l"(b), "l"(c)); return r;
}

__device__ __forceinline__ void combine26(float* r, const float* t) {
#pragma unroll
    for (int j = 0; j < 6; j++) {
        float n0 = fmaxf(r[2 * j], t[2 * j]);
        float n1 = fmaxf(fminf(r[2 * j], t[2 * j]),
                         fmaxf(r[2 * j + 1], t[2 * j + 1]));
        r[2 * j] = n0;
        r[2 * j + 1] = n1;
    }
#pragma unroll
    for (int i = 12; i < NQ; i++) r[i] += t[i];
}

__global__ __launch_bounds__(NT, 3)
void fused_kernel(const float* __restrict__ t1, const float* __restrict__ t2,
                  const float* __restrict__ t3, const float* __restrict__ t4,
                  const float* __restrict__ t5, const float* __restrict__ os,
                  const int* __restrict__ tg, float* __restrict__ out) {
    extern __shared__ float4 sbuf[];   // [WPB][NSTAGE][6][32] float4 = 72KB

    const int tid  = threadIdx.x;
    const int lane = tid & 31;
    const int wid  = tid >> 5;
    const int row  = blockIdx.x * WPB + wid;
    const long base = (long)row * NCOLS;
    const int target = __ldg(tg + row);

    // Packed constants (lane-duplicated)
    const u64 C02  = pk(0.2f, 0.2f);
    const u64 CIT  = pk(0.05f, 0.05f);          // 1/T_KD
    const u64 CONE = pk(1.0f, 1.0f);
    const u64 C2   = pk(0.5f, 0.5f);
    const u64 C3   = pk(1.0f / 6.0f, 1.0f / 6.0f);
    const u64 C4   = pk(1.0f / 24.0f, 1.0f / 24.0f);

    // Packed accumulators
    u64 S1[6], S2[6], r12p = 0ull, r13p = 0ull;
    float m0[6], m1[6];
#pragma unroll
    for (int j = 0; j < 6; j++) { S1[j] = 0ull; S2[j] = 0ull; m0[j] = -FLT_MAX; m1[j] = -FLT_MAX; }

    const float4* p0 = (const float4*)(t1 + base);
    const float4* p1 = (const float4*)(t2 + base);
    const float4* p2 = (const float4*)(t3 + base);
    const float4* p3 = (const float4*)(t4 + base);
    const float4* p4 = (const float4*)(t5 + base);
    const float4* ps = (const float4*)(os + base);

    // cp.async byte address base for this thread's slot
    u32 swb;
    {
        void* gp = (void*)(sbuf);
        u32 b;
        asm("{ .reg .u64 tmp; cvta.to.shared.u64 tmp, %1; cvt.u32.u64 %0, tmp; }"
            : "=r"(b) : "l"(gp));
        swb = b + (u32)wid * (NSTAGE * 6 * 32 * 16) + (u32)lane * 16;
    }
    // LDS base (float4 units) for this warp
    float4* lb = sbuf + (size_t)wid * (NSTAGE * 6 * 32) + lane;

    // Issue one stage's 6 async 16B copies (predicated per lane), then commit.
#define ISSUE(s)                                                                \
    {                                                                           \
        const int q_ = (s) * 32 + lane;                                         \
        if (q_ < 250) {                                                         \
            u32 d_ = swb + (u32)(((s) % NSTAGE) * (6 * 32 * 16));               \
            asm volatile("cp.async.cg.shared.global [%0], [%1], 16;"            \
                         :: "r"(d_ + 0 * 512), "l"(p0 + q_));                   \
            asm volatile("cp.async.cg.shared.global [%0], [%1], 16;"            \
                         :: "r"(d_ + 1 * 512), "l"(p1 + q_));                   \
            asm volatile("cp.async.cg.shared.global [%0], [%1], 16;"            \
                         :: "r"(d_ + 2 * 512), "l"(p2 + q_));                   \
            asm volatile("cp.async.cg.shared.global [%0], [%1], 16;"            \
                         :: "r"(d_ + 3 * 512), "l"(p3 + q_));                   \
            asm volatile("cp.async.cg.shared.global [%0], [%1], 16;"            \
                         :: "r"(d_ + 4 * 512), "l"(p4 + q_));                   \
            asm volatile("cp.async.cg.shared.global [%0], [%1], 16;"            \
                         :: "r"(d_ + 5 * 512), "l"(ps + q_));                   \
        }                                                                       \
        asm volatile("cp.async.commit_group;");                                 \
    }

    // Process one packed column pair. e^y via degree-4 poly (|y| <= ~0.3).
#define PAIR(xl0, xh0, xl1, xh1, xl2, xh2, xl3, xh3, xl4, xh4, sl, sh)       \
    {                                                                        \
        u64 d0 = pk(xl0, xh0), d1 = pk(xl1, xh1), d2 = pk(xl2, xh2);         \
        u64 d3 = pk(xl3, xh3), d4 = pk(xl4, xh4), ds = pk(sl, sh);           \
        u64 mm_ = vmul(vadd(vadd(vadd(d0, d1), vadd(d2, d3)), d4), C02);     \
        float2 mf_ = upk(mm_);                                               \
        u64 ys_ = vmul(ds, CIT);                                             \
        u64 tu_ = vfma(ys_, C4, C3);                                         \
        tu_ = vfma(ys_, tu_, C2);                                            \
        tu_ = vfma(ys_, tu_, CONE);                                          \
        u64 u_  = vfma(ys_, tu_, CONE);   /* e^{s/T} */                      \
        r13p = vadd(r13p, u_);                                               \
        u64 u2_ = vmul(u_, u_);                                              \
        u64 u4_ = vmul(u2_, u2_);                                            \
        u64 u5_ = vmul(u4_, u_);                                             \
        u64 u10_ = vmul(u5_, u5_);                                           \
        r12p = vfma(u10_, u10_, r12p);    /* e^s = u^20 */                   \
        u64 xs_[6] = {d0, d1, d2, d3, d4, mm_};                              \
        float xlo_[6] = {xl0, xl1, xl2, xl3, xl4, mf_.x};                    \
        float xhi_[6] = {xh0, xh1, xh2, xh3, xh4, mf_.y};                    \
        _Pragma("unroll")                                                    \
        for (int j = 0; j < 6; j++) {                                        \
            u64 y_ = vmul(xs_[j], CIT);                                      \
            u64 t_ = vfma(y_, C4, C3);                                       \
            t_ = vfma(y_, t_, C2);                                           \
            t_ = vfma(y_, t_, CONE);                                         \
            u64 e_ = vfma(y_, t_, CONE);                                     \
            S1[j] = vadd(S1[j], e_);                                         \
            S2[j] = vfma(e_, ys_, S2[j]);                                    \
            m1[j] = fmaxf(m1[j], fminf(m0[j], xlo_[j]));                     \
            m0[j] = fmaxf(m0[j], xlo_[j]);                                   \
            m1[j] = fmaxf(m1[j], fminf(m0[j], xhi_[j]));                     \
            m0[j] = fmaxf(m0[j], xhi_[j]);                                   \
        }                                                                    \
    }

#define COMPUTE(s)                                                           \
    {                                                                        \
        if ((s) * 32 + lane < 250) {                                         \
            const float4* b_ = lb + ((s) % NSTAGE) * (6 * 32);               \
            float4 v0 = b_[0 * 32];                                          \
            float4 v1 = b_[1 * 32];                                          \
            float4 v2 = b_[2 * 32];                                          \
            float4 v3 = b_[3 * 32];                                          \
            float4 v4 = b_[4 * 32];                                          \
            float4 vs = b_[5 * 32];                                          \
            PAIR(v0.x, v0.y, v1.x, v1.y, v2.x, v2.y,                         \
                 v3.x, v3.y, v4.x, v4.y, vs.x, vs.y)                         \
            PAIR(v0.z, v0.w, v1.z, v1.w, v2.z, v2.w,                         \
                 v3.z, v3.w, v4.z, v4.w, vs.z, vs.w)                         \
        }                                                                    \
    }

    // ---- Pipelined stream over 8 stages (stage s covers float4[s*32 + lane]) ----
    ISSUE(0)
    ISSUE(1)
#pragma unroll
    for (int s = 0; s < 8; s++) {
        if (s < 7) { asm volatile("cp.async.wait_group 1;"); }
        else       { asm volatile("cp.async.wait_group 0;"); }
        if (s < 6) { ISSUE(s + 2) }
        COMPUTE(s)
    }
#undef COMPUTE
#undef PAIR
#undef ISSUE

    // ---- Target logits (deferred; L2-hot; uniform per warp) ----
    float tq[7];
    tq[0] = __ldg(t1 + base + target);
    tq[1] = __ldg(t2 + base + target);
    tq[2] = __ldg(t3 + base + target);
    tq[3] = __ldg(t4 + base + target);
    tq[4] = __ldg(t5 + base + target);
    tq[6] = __ldg(os + base + target);
    tq[5] = (((tq[0] + tq[1]) + (tq[2] + tq[3])) + tq[4]) * 0.2f;  // same assoc as packed mimic

    // ---- Fold packed accumulators to 26 scalars ----
    float r[NQ];
#pragma unroll
    for (int j = 0; j < 6; j++) { r[2 * j] = m0[j]; r[2 * j + 1] = m1[j]; }
    { float2 f = upk(r12p); r[12] = f.x + f.y; }
    { float2 f = upk(r13p); r[13] = f.x + f.y; }
#pragma unroll
    for (int j = 0; j < 6; j++) { float2 f = upk(S1[j]); r[14 + j] = f.x + f.y; }
#pragma unroll
    for (int j = 0; j < 6; j++) { float2 f = upk(S2[j]); r[20 + j] = f.x + f.y; }

    // ---- Single warp-level reduction of all 26 quantities ----
#pragma unroll
    for (int o = 16; o > 0; o >>= 1) {
        float t[NQ];
#pragma unroll
        for (int i = 0; i < NQ; i++) t[i] = __shfl_xor_sync(0xffffffffu, r[i], o);
        combine26(r, t);
    }

    if (lane == 0) {
        const float T2      = 400.f;   // T_KD^2
        const float INV_TTH = 0.5f;    // 1/T_TH

        float CE   = __logf(r[12]) - tq[6];
        float lseT = __logf(r[13]);

        float tmax = r[0];
#pragma unroll
        for (int j = 1; j < 5; j++) tmax = fmaxf(tmax, r[2 * j]);

        float margins[6], kd[6];
#pragma unroll
        for (int j = 0; j < 6; j++) {
            kd[j]      = -T2 * (r[20 + j] / r[14 + j] - lseT);
            margins[j] = (tq[j] == r[2 * j]) ? (r[2 * j] - r[2 * j + 1]) : 0.f;
        }
        float mm = margins[0];
#pragma unroll
        for (int j = 1; j < 6; j++) mm = fmaxf(mm, margins[j]);
        float se = 0.f, A = 0.f;
#pragma unroll
        for (int j = 0; j < 6; j++) {
            float e = __expf((margins[j] - mm) * INV_TTH);
            se += e;
            A  += e * tq[j] * (kd[j] - CE);
        }
        g_ce[row] = CE;
        g_a[row]  = A / se;
        g_mx[row] = tmax;
        __threadfence();   // order this row's results before the ticket bump
    }

    // ---- last-block finalize ----
    __shared__ bool amLast;
    __shared__ float s1[WPB], s2[WPB], s3[WPB];
    __syncthreads();
    if (tid == 0) {
        int t = atomicAdd(&g_ticket, 1);
        amLast = (t == NB - 1);
    }
    __syncthreads();
    if (!amLast) return;
    __threadfence();

    const float4* c4 = (const float4*)g_ce;
    const float4* a4 = (const float4*)g_a;
    const float4* m4 = (const float4*)g_mx;

    float ce = 0.f, a = 0.f, mx = -FLT_MAX;
#pragma unroll
    for (int i = 0; i < 8; i++) {          // 2048 float4 per array / 256 threads
        int idx = tid + i * NT;
        float4 c = c4[idx], aa = a4[idx], m = m4[idx];
        ce += (c.x + c.y) + (c.z + c.w);
        a  += (aa.x + aa.y) + (aa.z + aa.w);
        mx  = fmaxf(mx, fmaxf(fmaxf(m.x, m.y), fmaxf(m.z, m.w)));
    }
#pragma unroll
    for (int o = 16; o > 0; o >>= 1) {
        ce += __shfl_xor_sync(0xffffffffu, ce, o);
        a  += __shfl_xor_sync(0xffffffffu, a, o);
        mx  = fmaxf(mx, __shfl_xor_sync(0xffffffffu, mx, o));
    }
    if (lane == 0) { s1[wid] = ce; s2[wid] = a; s3[wid] = mx; }
    __syncthreads();
    if (wid == 0) {
        ce = (lane < WPB) ? s1[lane] : 0.f;
        a  = (lane < WPB) ? s2[lane] : 0.f;
        mx = (lane < WPB) ? s3[lane] : -FLT_MAX;
#pragma unroll
        for (int o = 4; o > 0; o >>= 1) {
            ce += __shfl_xor_sync(0xffffffffu, ce, o);
            a  += __shfl_xor_sync(0xffffffffu, a, o);
            mx  = fmaxf(mx, __shfl_xor_sync(0xffffffffu, mx, o));
        }
        if (lane == 0) {
            const float invB = 1.0f / (float)NROWS;
            out[0] = ce * invB + (0.8f / mx) * (a * invB);
            g_ticket = 0;   // reset for next graph replay (deterministic)
        }
    }
}

extern "C" void kernel_launch(void* const* d_in, const int* in_sizes, int n_in,
                              void* d_out, int out_size) {
    const float* t1 = (const float*)d_in[0];
    const float* t2 = (const float*)d_in[1];
    const float* t3 = (const float*)d_in[2];
    const float* t4 = (const float*)d_in[3];
    const float* t5 = (const float*)d_in[4];
    const float* os = (const float*)d_in[5];
    const int*   tg = (const int*)d_in[6];

    const int smem = WPB * NSTAGE * 6 * 32 * 16;   // 73728 B
    cudaFuncSetAttribute(fused_kernel, cudaFuncAttributeMaxDynamicSharedMemorySize, smem);
    fused_kernel<<<NB, NT, smem>>>(t1, t2, t3, t4, t5, os, tg, (float*)d_out);
}

// round 9
// speedup vs baseline: 1.1648x; 1.1648x over previous
#include <cuda_runtime.h>
#include <stdint.h>
#include <float.h>

#define NROWS 8192
#define NCOLS 1000
#define NT 256
#define WPB 8                 // warps (rows) per block
#define NB (NROWS / WPB)      // 1024 blocks
#define NQ 26
// r[0..11]  : top2 pairs for 6 sources (max, second)
// r[12]     : sum e^{s}
// r[13]     : sum e^{s/T}
// r[14+j]   : S1_j = sum e^{x_j/T}
// r[20+j]   : S2_j = sum e^{x_j/T} * (s/T)

__device__ float g_ce[NROWS];
__device__ float g_a[NROWS];
__device__ float g_mx[NROWS];
__device__ int   g_ticket;    // zero-init; reset by last block each run

__device__ __forceinline__ void combine26(float* r, const float* t) {
#pragma unroll
    for (int j = 0; j < 6; j++) {
        float n0 = fmaxf(r[2 * j], t[2 * j]);
        float n1 = fmaxf(fminf(r[2 * j], t[2 * j]),
                         fmaxf(r[2 * j + 1], t[2 * j + 1]));
        r[2 * j] = n0;
        r[2 * j + 1] = n1;
    }
#pragma unroll
    for (int i = 12; i < NQ; i++) r[i] += t[i];
}

__global__ __launch_bounds__(NT, 3)
void fused_kernel(const float* __restrict__ t1, const float* __restrict__ t2,
                  const float* __restrict__ t3, const float* __restrict__ t4,
                  const float* __restrict__ t5, const float* __restrict__ os,
                  const int* __restrict__ tg, float* __restrict__ out) {
    const int tid  = threadIdx.x;
    const int lane = tid & 31;
    const int wid  = tid >> 5;
    const int row  = blockIdx.x * WPB + wid;
    const long base = (long)row * NCOLS;
    const int target = __ldg(tg + row);

    const float INV_T   = 0.05f;   // 1/T_KD
    const float T2      = 400.f;   // T_KD^2
    const float INV_TTH = 0.5f;    // 1/T_TH

    // ---- Target logits up-front (uniform address per warp = broadcast) ----
    float tq[7];
    tq[0] = __ldg(t1 + base + target);
    tq[1] = __ldg(t2 + base + target);
    tq[2] = __ldg(t3 + base + target);
    tq[3] = __ldg(t4 + base + target);
    tq[4] = __ldg(t5 + base + target);
    tq[6] = __ldg(os + base + target);
    tq[5] = (tq[0] + tq[1] + tq[2] + tq[3] + tq[4]) * 0.2f;

    float r[NQ];
#pragma unroll
    for (int i = 0; i < 12; i++) r[i] = -FLT_MAX;
#pragma unroll
    for (int i = 12; i < NQ; i++) r[i] = 0.f;

    const float4* p0 = (const float4*)(t1 + base);
    const float4* p1 = (const float4*)(t2 + base);
    const float4* p2 = (const float4*)(t3 + base);
    const float4* p3 = (const float4*)(t4 + base);
    const float4* p4 = (const float4*)(t5 + base);
    const float4* ps = (const float4*)(os + base);

    // L2 prefetch: 4 lanes cover the 4 x 128B lines of the warp's 512B region
    // for each tensor, 2 iterations ahead. No registers held, no scoreboard.
#define PREF(qbase)                                                           \
    if (lane < 4) {                                                           \
        const int qp_ = (qbase) + lane * 8;                                   \
        asm volatile("prefetch.global.L2 [%0];" :: "l"(p0 + qp_));            \
        asm volatile("prefetch.global.L2 [%0];" :: "l"(p1 + qp_));            \
        asm volatile("prefetch.global.L2 [%0];" :: "l"(p2 + qp_));            \
        asm volatile("prefetch.global.L2 [%0];" :: "l"(p3 + qp_));            \
        asm volatile("prefetch.global.L2 [%0];" :: "l"(p4 + qp_));            \
        asm volatile("prefetch.global.L2 [%0];" :: "l"(ps + qp_));            \
    }

#define BODY(q)                                                               \
    {                                                                         \
        float4 v0 = __ldg(p0 + (q));                                          \
        float4 v1 = __ldg(p1 + (q));                                          \
        float4 v2 = __ldg(p2 + (q));                                          \
        float4 v3 = __ldg(p3 + (q));                                          \
        float4 v4 = __ldg(p4 + (q));                                          \
        float4 vs = __ldg(ps + (q));                                          \
        float a0[4] = {v0.x, v0.y, v0.z, v0.w};                               \
        float a1[4] = {v1.x, v1.y, v1.z, v1.w};                               \
        float a2[4] = {v2.x, v2.y, v2.z, v2.w};                               \
        float a3[4] = {v3.x, v3.y, v3.z, v3.w};                               \
        float a4[4] = {v4.x, v4.y, v4.z, v4.w};                               \
        float as[4] = {vs.x, vs.y, vs.z, vs.w};                               \
        _Pragma("unroll")                                                     \
        for (int k = 0; k < 4; k++) {                                         \
            float m = (a0[k] + a1[k] + a2[k] + a3[k] + a4[k]) * 0.2f;         \
            float lpw = as[k] * INV_T;                                        \
            float u = __expf(lpw);                                            \
            float u2 = u * u, u4 = u2 * u2, u5 = u4 * u;                      \
            float u10 = u5 * u5;                                              \
            r[12] += u10 * u10; /* e^s = u^20 */                              \
            r[13] += u;                                                       \
            float x[6] = {a0[k], a1[k], a2[k], a3[k], a4[k], m};              \
            _Pragma("unroll")                                                 \
            for (int j = 0; j < 6; j++) {                                     \
                float xv = x[j];                                              \
                float e = __expf(xv * INV_T);                                 \
                r[14 + j] += e;                                               \
                r[20 + j] = fmaf(e, lpw, r[20 + j]);                          \
                float nm0 = fmaxf(r[2 * j], xv);                              \
                r[2 * j + 1] = fmaxf(r[2 * j + 1], fminf(r[2 * j], xv));      \
                r[2 * j] = nm0;                                               \
            }                                                                 \
        }                                                                     \
    }

    // Warm the pipe: prefetch iterations 0 and 1 into L2
    PREF(0)
    PREF(32)

    // 7 full iterations: warp covers float4[0..223]; prefetch it+2 each time
#pragma unroll 2
    for (int it = 0; it < 7; it++) {
        if (it < 6) { PREF((it + 2) * 32) }
        BODY(it * 32 + lane)
    }
    // tail: float4[224..249] (26 lanes)
    if (lane < 26) {
        BODY(224 + lane)
    }
#undef BODY
#undef PREF

    // ---- Single warp-level reduction of all 26 quantities ----
#pragma unroll
    for (int o = 16; o > 0; o >>= 1) {
        float t[NQ];
#pragma unroll
        for (int i = 0; i < NQ; i++) t[i] = __shfl_xor_sync(0xffffffffu, r[i], o);
        combine26(r, t);
    }

    if (lane == 0) {
        float CE   = __logf(r[12]) - tq[6];
        float lseT = __logf(r[13]);

        float tmax = r[0];
#pragma unroll
        for (int j = 1; j < 5; j++) tmax = fmaxf(tmax, r[2 * j]);

        float margins[6], kd[6];
#pragma unroll
        for (int j = 0; j < 6; j++) {
            kd[j]      = -T2 * (r[20 + j] / r[14 + j] - lseT);
            margins[j] = (tq[j] == r[2 * j]) ? (r[2 * j] - r[2 * j + 1]) : 0.f;
        }
        float mm = margins[0];
#pragma unroll
        for (int j = 1; j < 6; j++) mm = fmaxf(mm, margins[j]);
        float se = 0.f, A = 0.f;
#pragma unroll
        for (int j = 0; j < 6; j++) {
            float e = __expf((margins[j] - mm) * INV_TTH);
            se += e;
            A  += e * tq[j] * (kd[j] - CE);
        }
        g_ce[row] = CE;
        g_a[row]  = A / se;
        g_mx[row] = tmax;
        __threadfence();   // order this row's results before the ticket bump
    }

    // ---- last-block finalize ----
    __shared__ bool amLast;
    __shared__ float s1[WPB], s2[WPB], s3[WPB];
    __syncthreads();
    if (tid == 0) {
        int t = atomicAdd(&g_ticket, 1);
        amLast = (t == NB - 1);
    }
    __syncthreads();
    if (!amLast) return;
    __threadfence();

    const float4* c4 = (const float4*)g_ce;
    const float4* a4 = (const float4*)g_a;
    const float4* m4 = (const float4*)g_mx;

    float ce = 0.f, a = 0.f, mx = -FLT_MAX;
#pragma unroll
    for (int i = 0; i < 8; i++) {          // 2048 float4 per array / 256 threads
        int idx = tid + i * NT;
        float4 c = c4[idx], aa = a4[idx], m = m4[idx];
        ce += (c.x + c.y) + (c.z + c.w);
        a  += (aa.x + aa.y) + (aa.z + aa.w);
        mx  = fmaxf(mx, fmaxf(fmaxf(m.x, m.y), fmaxf(m.z, m.w)));
    }
#pragma unroll
    for (int o = 16; o > 0; o >>= 1) {
        ce += __shfl_xor_sync(0xffffffffu, ce, o);
        a  += __shfl_xor_sync(0xffffffffu, a, o);
        mx  = fmaxf(mx, __shfl_xor_sync(0xffffffffu, mx, o));
    }
    if (lane == 0) { s1[wid] = ce; s2[wid] = a; s3[wid] = mx; }
    __syncthreads();
    if (wid == 0) {
        ce = (lane < WPB) ? s1[lane] : 0.f;
        a  = (lane < WPB) ? s2[lane] : 0.f;
        mx = (lane < WPB) ? s3[lane] : -FLT_MAX;
#pragma unroll
        for (int o = 4; o > 0; o >>= 1) {
            ce += __shfl_xor_sync(0xffffffffu, ce, o);
            a  += __shfl_xor_sync(0xffffffffu, a, o);
            mx  = fmaxf(mx, __shfl_xor_sync(0xffffffffu, mx, o));
        }
        if (lane == 0) {
            const float invB = 1.0f / (float)NROWS;
            out[0] = ce * invB + (0.8f / mx) * (a * invB);
            g_ticket = 0;   // reset for next graph replay (deterministic)
        }
    }
}

extern "C" void kernel_launch(void* const* d_in, const int* in_sizes, int n_in,
                              void* d_out, int out_size) {
    const float* t1 = (const float*)d_in[0];
    const float* t2 = (const float*)d_in[1];
    const float* t3 = (const float*)d_in[2];
    const float* t4 = (const float*)d_in[3];
    const float* t5 = (const float*)d_in[4];
    const float* os = (const float*)d_in[5];
    const int*   tg = (const int*)d_in[6];

    fused_kernel<<<NB, NT>>>(t1, t2, t3, t4, t5, os, tg, (float*)d_out);
}